// round 10
// baseline (speedup 1.0000x reference)
#include <cuda_runtime.h>
#include <cuda_bf16.h>
#include <cstdint>
#include <math.h>

#define BB 2
#define TT 2048
#define DD 2048
#define HH 16
#define HD 128
#define ROWS (BB*TT)              // 4096
#define NQKV (3*DD)               // 6144
#define EPSV 1.1920929e-07f
#define ATT_SCALE 0.088388347648318447f   // 1/sqrt(128)

typedef __nv_bfloat16 bf16;

// ---------------- scratch (device globals) ----------------
__device__ __align__(256) bf16 d_xn_h [ROWS*DD], d_xn_l [ROWS*DD];       // rms(x)
__device__ __align__(256) bf16 d_wc_h [NQKV*DD], d_wc_l [NQKV*DD];       // [6144,K] gains folded
__device__ __align__(256) bf16 d_wo_h [DD*DD],   d_wo_l [DD*DD];         // [N,K]
__device__ __align__(256) float d_qkvlin[ROWS*NQKV];                     // [4096,6144]
__device__ __align__(256) bf16 d_qn_h[BB*HH*TT*HD], d_qn_l[BB*HH*TT*HD]; // [B,H,T,d]
__device__ __align__(256) bf16 d_kn_h[BB*HH*TT*HD], d_kn_l[BB*HH*TT*HD];
__device__ __align__(256) bf16 d_vt_h[BB*HH*HD*TT], d_vt_l[BB*HH*HD*TT]; // [B,H,d,T]
__device__ __align__(256) bf16 d_wvt_h[ROWS*DD], d_wvt_l[ROWS*DD];       // [B*T, D]

// ---------------- helpers ----------------
__device__ __forceinline__ void split2(float x, bf16& h, bf16& l) {
    h = __float2bfloat16(x);
    l = __float2bfloat16(x - __bfloat162float(h));
}

__device__ __forceinline__ uint32_t pack_bf2(bf16 a, bf16 b) {
    __nv_bfloat162 t = __halves2bfloat162(a, b);
    return *(uint32_t*)&t;
}

__device__ __forceinline__ float blockReduceSum(float v, float* sh) {
    __syncthreads();
    int lane = threadIdx.x & 31, w = threadIdx.x >> 5;
    #pragma unroll
    for (int o = 16; o > 0; o >>= 1) v += __shfl_down_sync(0xffffffffu, v, o);
    if (lane == 0) sh[w] = v;
    __syncthreads();
    int nw = blockDim.x >> 5;
    v = (threadIdx.x < nw) ? sh[threadIdx.x] : 0.0f;
    if (w == 0) {
        #pragma unroll
        for (int o = 16; o > 0; o >>= 1) v += __shfl_down_sync(0xffffffffu, v, o);
        if (lane == 0) sh[0] = v;
    }
    __syncthreads();
    return sh[0];
}

__device__ __forceinline__ uint32_t smem_u32(const void* p) {
    return (uint32_t)__cvta_generic_to_shared(p);
}

__device__ __forceinline__ void ldsm4(uint32_t addr, uint32_t* r) {
    asm volatile("ldmatrix.sync.aligned.m8n8.x4.shared.b16 {%0,%1,%2,%3}, [%4];"
                 : "=r"(r[0]), "=r"(r[1]), "=r"(r[2]), "=r"(r[3]) : "r"(addr));
}

__device__ __forceinline__ void mma16816(float* c, const uint32_t* a, const uint32_t* b) {
    asm volatile("mma.sync.aligned.m16n8k16.row.col.f32.bf16.bf16.f32 "
                 "{%0,%1,%2,%3}, {%4,%5,%6,%7}, {%8,%9}, {%0,%1,%2,%3};"
                 : "+f"(c[0]), "+f"(c[1]), "+f"(c[2]), "+f"(c[3])
                 : "r"(a[0]), "r"(a[1]), "r"(a[2]), "r"(a[3]), "r"(b[0]), "r"(b[1]));
}

__device__ __forceinline__ void cpasync16(uint32_t dst, const void* src) {
    asm volatile("cp.async.cg.shared.global [%0], [%1], 16;" :: "r"(dst), "l"(src));
}
__device__ __forceinline__ void cpcommit() {
    asm volatile("cp.async.commit_group;" ::: "memory");
}
template<int N> __device__ __forceinline__ void cpwait() {
    asm volatile("cp.async.wait_group %0;" :: "n"(N) : "memory");
}

// ---------------- mma.sync GEMM: 64x128 block, 128 threads (2x2 warps), 2 CTAs/SM ----
// C[M,N] = alpha*(A @ Bt^T)(+bias). A:[M,K] hi/lo; Bt:[N,K] hi/lo. K % 64 == 0.
// Per stage: Ah 8KB | Al 8KB | Bh 16KB | Bl 16KB = 48KB. 2 stages = 96KB.
// Fragments double-buffered: ldsm for step s+1 issued before step-s MMAs.
#define G_STAGE 49152
#define G_SMEM  (2*G_STAGE)
#define OFF_AL  8192
#define OFF_BH  16384
#define OFF_BL  32768

template<bool HAS_BIAS>
__global__ __launch_bounds__(128, 2)
void mma_gemm(const bf16* __restrict__ Ah, const bf16* __restrict__ Al,
              const bf16* __restrict__ Bh, const bf16* __restrict__ Bl,
              const float* __restrict__ bias, float* __restrict__ C,
              int K, int ldc, float alpha) {
    extern __shared__ char smem[];
    const uint32_t sb = smem_u32(smem);
    const int tid = threadIdx.x, lane = tid & 31, w = tid >> 5;
    const int wm = w >> 1, wn = w & 1;          // warp grid 2(M) x 2(N)
    const int bm = blockIdx.y * 64, bn = blockIdx.x * 128;

    const bf16* aSrcs[2] = { Ah + (size_t)bm * K, Al + (size_t)bm * K };
    const bf16* bSrcs[2] = { Bh + (size_t)bn * K, Bl + (size_t)bn * K };

    // precomputed ldsm row offsets (XOR-composable with (c16<<4))
    uint32_t aRel[2], bRel[4];
    #pragma unroll
    for (int t = 0; t < 2; t++) {
        int m = wm * 32 + t * 16 + (lane & 15);
        aRel[t] = (uint32_t)(m * 128 + ((m & 7) << 4));
    }
    #pragma unroll
    for (int u = 0; u < 4; u++) {
        int n = wn * 64 + u * 16 + (lane & 15);
        bRel[u] = (uint32_t)(n * 128 + ((n & 7) << 4));
    }
    const uint32_t cbase = (uint32_t)(lane >> 4) << 4;

    float acc[2][8][4];
    #pragma unroll
    for (int t = 0; t < 2; t++)
        #pragma unroll
        for (int n = 0; n < 8; n++)
            #pragma unroll
            for (int r = 0; r < 4; r++) acc[t][n][r] = 0.0f;

    const int NC = K >> 6;

    auto issue_load = [&](int stage, int kc) {
        const uint32_t base = sb + stage * G_STAGE;
        const int k0 = kc << 6;
        #pragma unroll
        for (int t = 0; t < 2; t++) {           // A hi/lo: 64 rows x 8 cols of 16B
            const bf16* sp = aSrcs[t] + k0;
            const uint32_t tb = base + t * OFF_AL;
            #pragma unroll
            for (int j = 0; j < 4; j++) {
                int f = tid + j * 128;
                int r = f >> 3, c = f & 7;
                cpasync16(tb + (uint32_t)(r * 128 + ((c ^ (r & 7)) << 4)),
                          sp + (size_t)r * K + c * 8);
            }
        }
        #pragma unroll
        for (int t = 0; t < 2; t++) {           // B hi/lo: 128 rows x 8 cols of 16B
            const bf16* sp = bSrcs[t] + k0;
            const uint32_t tb = base + OFF_BH + t * (OFF_BL - OFF_BH);
            #pragma unroll
            for (int j = 0; j < 8; j++) {
                int f = tid + j * 128;
                int r = f >> 3, c = f & 7;
                cpasync16(tb + (uint32_t)(r * 128 + ((c ^ (r & 7)) << 4)),
                          sp + (size_t)r * K + c * 8);
            }
        }
        cpcommit();
    };

    // double-buffered fragments
    uint32_t aH[2][2][4], aL[2][2][4], bH[2][8][2], bL[2][8][2];

    issue_load(0, 0);
    for (int kc = 0; kc < NC; kc++) {
        const int cur = kc & 1;
        if (kc + 1 < NC) { issue_load(cur ^ 1, kc + 1); cpwait<1>(); }
        else             { cpwait<0>(); }
        __syncthreads();

        const uint32_t baseA  = sb + cur * G_STAGE;
        const uint32_t baseAL = baseA + OFF_AL;
        const uint32_t baseBH = baseA + OFF_BH;
        const uint32_t baseBL = baseA + OFF_BL;

        // load step s into frag set p (p must be compile-time under full unroll)
        auto ldstep = [&](int s, int p) {
            const uint32_t xv = (uint32_t)((2 * s) << 4) ^ cbase;
            #pragma unroll
            for (int t = 0; t < 2; t++) {
                uint32_t off = aRel[t] ^ xv;
                ldsm4(baseA  + off, aH[p][t]);
                ldsm4(baseAL + off, aL[p][t]);
            }
            #pragma unroll
            for (int u = 0; u < 4; u++) {
                uint32_t off = bRel[u] ^ xv;
                uint32_t r4[4];
                ldsm4(baseBH + off, r4);
                bH[p][2*u][0] = r4[0]; bH[p][2*u+1][0] = r4[1];
                bH[p][2*u][1] = r4[2]; bH[p][2*u+1][1] = r4[3];
                ldsm4(baseBL + off, r4);
                bL[p][2*u][0] = r4[0]; bL[p][2*u+1][0] = r4[1];
                bL[p][2*u][1] = r4[2]; bL[p][2*u+1][1] = r4[3];
            }
        };

        ldstep(0, 0);
        #pragma unroll
        for (int s = 0; s < 4; s++) {
            const int p = s & 1;
            if (s + 1 < 4) ldstep(s + 1, p ^ 1);   // prefetch next step's frags
            #pragma unroll
            for (int t = 0; t < 2; t++)
                #pragma unroll
                for (int n = 0; n < 8; n++) {
                    mma16816(acc[t][n], aH[p][t], bH[p][n]);
                    mma16816(acc[t][n], aH[p][t], bL[p][n]);
                    mma16816(acc[t][n], aL[p][t], bH[p][n]);
                }
        }
        __syncthreads();
    }

    #pragma unroll
    for (int t = 0; t < 2; t++) {
        #pragma unroll
        for (int n = 0; n < 8; n++) {
            int m0 = bm + wm * 32 + t * 16 + (lane >> 2);
            int n0 = bn + wn * 64 + n * 8 + 2 * (lane & 3);
            float bx = 0.0f, by = 0.0f;
            if (HAS_BIAS) { bx = bias[n0]; by = bias[n0 + 1]; }
            float2 v0 = { acc[t][n][0] * alpha + bx, acc[t][n][1] * alpha + by };
            float2 v1 = { acc[t][n][2] * alpha + bx, acc[t][n][3] * alpha + by };
            *(float2*)(C + (size_t)m0 * ldc + n0) = v0;
            *(float2*)(C + (size_t)(m0 + 8) * ldc + n0) = v1;
        }
    }
}

// ---------------- fused flash attention (unchanged) ----------------
#define FSEG 32768
#define SMEM_FLASH (6*FSEG)

__device__ __forceinline__ uint32_t swz(int r, int c) {
    return (uint32_t)(r * 256 + (((c & 8) | ((c ^ r) & 7)) << 4));
}

__global__ __launch_bounds__(256, 1)
void flash_kernel() {
    extern __shared__ char smem[];
    const uint32_t sb = smem_u32(smem);
    const uint32_t sKh = sb, sKl = sb + FSEG, sVh = sb + 2*FSEG, sVl = sb + 3*FSEG;
    const uint32_t sQh = sb + 4*FSEG, sQl = sb + 5*FSEG;

    const int tid = threadIdx.x, lane = tid & 31, w = tid >> 5;
    const int bh = blockIdx.y;
    const int q0 = blockIdx.x * 128;

    const bf16* qh = d_qn_h + (size_t)bh * TT * HD + (size_t)q0 * HD;
    const bf16* ql = d_qn_l + (size_t)bh * TT * HD + (size_t)q0 * HD;
    const bf16* kh = d_kn_h + (size_t)bh * TT * HD;
    const bf16* kl = d_kn_l + (size_t)bh * TT * HD;
    const bf16* vh = d_vt_h + (size_t)bh * HD * TT;
    const bf16* vl = d_vt_l + (size_t)bh * HD * TT;

    auto loadT = [&](uint32_t dstb, const bf16* src, int rowStride) {
        #pragma unroll
        for (int j = 0; j < 8; j++) {
            int f = tid + j * 256;
            int r = f >> 4, c = f & 15;
            cpasync16(dstb + swz(r, c), src + (size_t)r * rowStride + c * 8);
        }
    };

    loadT(sQh, qh, HD); loadT(sQl, ql, HD);
    loadT(sKh, kh, HD); loadT(sKl, kl, HD);
    loadT(sVh, vh, TT); loadT(sVl, vl, TT);
    cpcommit();
    cpwait<0>();
    __syncthreads();

    float o[16][4];
    #pragma unroll
    for (int f = 0; f < 16; f++)
        #pragma unroll
        for (int j = 0; j < 4; j++) o[f][j] = 0.0f;
    float mrow[2] = {-INFINITY, -INFINITY};
    float lrow[2] = {0.0f, 0.0f};

    const int NT = TT / 128;
    for (int i = 0; i < NT; i++) {
        float sacc[16][4];
        #pragma unroll
        for (int f = 0; f < 16; f++)
            #pragma unroll
            for (int j = 0; j < 4; j++) sacc[f][j] = 0.0f;

        #pragma unroll
        for (int s = 0; s < 8; s++) {
            const int mR = (w << 4) + (lane & 15);
            const int cc = 2 * s + (lane >> 4);
            uint32_t aH[4], aL[4];
            ldsm4(sQh + swz(mR, cc), aH);
            ldsm4(sQl + swz(mR, cc), aL);
            #pragma unroll
            for (int u = 0; u < 8; u++) {
                const int n = u * 16 + (lane & 15);
                uint32_t r4h[4], r4l[4];
                ldsm4(sKh + swz(n, cc), r4h);
                ldsm4(sKl + swz(n, cc), r4l);
                uint32_t b0h[2] = {r4h[0], r4h[2]}, b1h[2] = {r4h[1], r4h[3]};
                uint32_t b0l[2] = {r4l[0], r4l[2]}, b1l[2] = {r4l[1], r4l[3]};
                mma16816(sacc[2*u],   aH, b0h);
                mma16816(sacc[2*u],   aH, b0l);
                mma16816(sacc[2*u],   aL, b0h);
                mma16816(sacc[2*u+1], aH, b1h);
                mma16816(sacc[2*u+1], aH, b1l);
                mma16816(sacc[2*u+1], aL, b1h);
            }
        }
        __syncthreads();
        if (i + 1 < NT) { loadT(sKh, kh + (size_t)(i+1)*128*HD, HD);
                          loadT(sKl, kl + (size_t)(i+1)*128*HD, HD); cpcommit(); }

        float mnew[2] = {mrow[0], mrow[1]};
        #pragma unroll
        for (int f = 0; f < 16; f++) {
            mnew[0] = fmaxf(mnew[0], fmaxf(sacc[f][0], sacc[f][1]));
            mnew[1] = fmaxf(mnew[1], fmaxf(sacc[f][2], sacc[f][3]));
        }
        #pragma unroll
        for (int rr = 0; rr < 2; rr++) {
            mnew[rr] = fmaxf(mnew[rr], __shfl_xor_sync(0xffffffffu, mnew[rr], 1));
            mnew[rr] = fmaxf(mnew[rr], __shfl_xor_sync(0xffffffffu, mnew[rr], 2));
        }
        float resc[2] = { __expf(mrow[0] - mnew[0]), __expf(mrow[1] - mnew[1]) };
        mrow[0] = mnew[0]; mrow[1] = mnew[1];
        float psum[2] = {0.0f, 0.0f};
        #pragma unroll
        for (int f = 0; f < 16; f++) {
            sacc[f][0] = __expf(sacc[f][0] - mrow[0]);
            sacc[f][1] = __expf(sacc[f][1] - mrow[0]);
            sacc[f][2] = __expf(sacc[f][2] - mrow[1]);
            sacc[f][3] = __expf(sacc[f][3] - mrow[1]);
            psum[0] += sacc[f][0] + sacc[f][1];
            psum[1] += sacc[f][2] + sacc[f][3];
        }
        #pragma unroll
        for (int rr = 0; rr < 2; rr++) {
            psum[rr] += __shfl_xor_sync(0xffffffffu, psum[rr], 1);
            psum[rr] += __shfl_xor_sync(0xffffffffu, psum[rr], 2);
        }
        lrow[0] = lrow[0] * resc[0] + psum[0];
        lrow[1] = lrow[1] * resc[1] + psum[1];
        #pragma unroll
        for (int f = 0; f < 16; f++) {
            o[f][0] *= resc[0]; o[f][1] *= resc[0];
            o[f][2] *= resc[1]; o[f][3] *= resc[1];
        }

        if (i > 0) {
            if (i + 1 < NT) cpwait<1>(); else cpwait<0>();
            __syncthreads();
        }

        #pragma unroll
        for (int s = 0; s < 8; s++) {
            const int f0 = 2 * s, f1 = 2 * s + 1;
            uint32_t aPh[4], aPl[4];
            {
                bf16 h00, l00, h01, l01, h02, l02, h03, l03;
                split2(sacc[f0][0], h00, l00); split2(sacc[f0][1], h01, l01);
                split2(sacc[f0][2], h02, l02); split2(sacc[f0][3], h03, l03);
                aPh[0] = pack_bf2(h00, h01); aPh[1] = pack_bf2(h02, h03);
                aPl[0] = pack_bf2(l00, l01); aPl[1] = pack_bf2(l02, l03);
                split2(sacc[f1][0], h00, l00); split2(sacc[f1][1], h01, l01);
                split2(sacc[f1][2], h02, l02); split2(sacc[f1][3], h03, l03);
                aPh[2] = pack_bf2(h00, h01); aPh[3] = pack_bf2(h02, h03);
                aPl[2] = pack_bf2(l00, l01); aPl[3] = pack_bf2(l02, l03);
            }
            const int cc = 2 * s + (lane >> 4);
            #pragma unroll
            for (int u = 0; u < 8; u++) {
                const int n = u * 16 + (lane & 15);
                uint32_t r4h[4], r4l[4];
                ldsm4(sVh + swz(n, cc), r4h);
                ldsm4(sVl + swz(n, cc), r4l);
                uint32_t b0h[2] = {r4h[0], r4h[2]}, b1h[2] = {r4h[1], r4h[3]};
                uint32_t b0l[2] = {r4l[0], r4l[2]}, b1l[2] = {r4l[1], r4l[3]};
                mma16816(o[2*u],   aPh, b0h);
                mma16816(o[2*u],   aPh, b0l);
                mma16816(o[2*u],   aPl, b0h);
                mma16816(o[2*u+1], aPh, b1h);
                mma16816(o[2*u+1], aPh, b1l);
                mma16816(o[2*u+1], aPl, b1h);
            }
        }
        __syncthreads();
        if (i + 1 < NT) {
            loadT(sVh, vh + (size_t)(i+1)*128, TT);
            loadT(sVl, vl + (size_t)(i+1)*128, TT);
            cpcommit();
            cpwait<1>();
            __syncthreads();
        }
    }

    const int b = bh >> 4, h = bh & 15;
    const float inv0 = 1.0f / lrow[0], inv1 = 1.0f / lrow[1];
    const int r0 = (w << 4) + (lane >> 2);
    const size_t bt0 = (size_t)(b * TT + q0 + r0) * DD;
    const size_t bt1 = (size_t)(b * TT + q0 + r0 + 8) * DD;
    const int colb = h * HD + 2 * (lane & 3);
    #pragma unroll
    for (int f = 0; f < 16; f++) {
        const int col = colb + f * 8;
        bf16 h0, l0, h1, l1;
        split2(o[f][0] * inv0, h0, l0); split2(o[f][1] * inv0, h1, l1);
        *(uint32_t*)(d_wvt_h + bt0 + col) = pack_bf2(h0, h1);
        *(uint32_t*)(d_wvt_l + bt0 + col) = pack_bf2(l0, l1);
        split2(o[f][2] * inv1, h0, l0); split2(o[f][3] * inv1, h1, l1);
        *(uint32_t*)(d_wvt_h + bt1 + col) = pack_bf2(h0, h1);
        *(uint32_t*)(d_wvt_l + bt1 + col) = pack_bf2(l0, l1);
    }
}

// ---------------- elementwise producers ----------------
__global__ void rmsnorm_kernel(const float* __restrict__ x) {
    int row = blockIdx.x;
    const float* xr = x + (size_t)row * DD;
    float s = 0.0f;
    for (int c = threadIdx.x; c < DD; c += blockDim.x) { float v = xr[c]; s += v * v; }
    __shared__ float sh[32];
    s = blockReduceSum(s, sh);
    float inv = rsqrtf(s * (1.0f / DD) + EPSV);
    for (int c = threadIdx.x; c < DD; c += blockDim.x) {
        size_t o = (size_t)row * DD + c;
        bf16 h, l;
        split2(xr[c] * inv, h, l);
        d_xn_h[o] = h; d_xn_l[o] = l;
    }
}

__global__ void wtransg_kernel(const float* __restrict__ W, const float* __restrict__ g,
                               bf16* __restrict__ Th, bf16* __restrict__ Tl,
                               int Nd, int rowOff) {
    __shared__ float tile[32][33];
    int k0 = blockIdx.y * 32, n0 = blockIdx.x * 32;
    for (int j = threadIdx.y; j < 32; j += 8)
        tile[j][threadIdx.x] = W[(size_t)(k0 + j) * Nd + n0 + threadIdx.x];
    __syncthreads();
    float gv = g ? g[k0 + threadIdx.x] : 1.0f;
    for (int j = threadIdx.y; j < 32; j += 8) {
        float v = tile[threadIdx.x][j] * gv;
        bf16 h, l; split2(v, h, l);
        size_t o = (size_t)(rowOff + n0 + j) * DD + k0 + threadIdx.x;
        Th[o] = h; Tl[o] = l;
    }
}

__global__ void head_rms_kernel(const float* __restrict__ ghead,
                                const float* __restrict__ bq,
                                const float* __restrict__ bkv) {
    int bid = blockIdx.x;
    int t = bid & (TT - 1);
    int bh = bid / TT;
    int h = bh & (HH - 1);
    int b = bh / HH;
    int bt = b * TT + t;
    int i = threadIdx.x;
    int col = h * HD + i;

    float qv = d_qkvlin[(size_t)bt * NQKV + col] + bq[col];
    float kv = d_qkvlin[(size_t)bt * NQKV + DD + col] + bkv[col];

    __shared__ float sh[32];
    float sq = blockReduceSum(qv * qv, sh);
    float sk = blockReduceSum(kv * kv, sh);

    float g = ghead[i];
    size_t o = (size_t)bid * HD + i;
    float qn = qv * rsqrtf(sq * (1.0f / HD) + EPSV) * g * ATT_SCALE;
    float kn = kv * rsqrtf(sk * (1.0f / HD) + EPSV) * g;
    bf16 hh, ll;
    split2(qn, hh, ll); d_qn_h[o] = hh; d_qn_l[o] = ll;
    split2(kn, hh, ll); d_kn_h[o] = hh; d_kn_l[o] = ll;
}

__global__ void vtrans_kernel(const float* __restrict__ bkv) {
    __shared__ float tile[32][33];
    int bh = blockIdx.z;
    int b = bh >> 4, h = bh & 15;
    int t0 = blockIdx.x * 32, i0 = blockIdx.y * 32;
    for (int j = threadIdx.y; j < 32; j += 8)
        tile[j][threadIdx.x] =
            d_qkvlin[(size_t)(b * TT + t0 + j) * NQKV + 2 * DD + h * HD + i0 + threadIdx.x];
    __syncthreads();
    for (int j = threadIdx.y; j < 32; j += 8) {
        float v = tile[threadIdx.x][j] + bkv[DD + h * HD + i0 + j];
        bf16 hh, ll; split2(v, hh, ll);
        size_t o = ((size_t)bh * HD + i0 + j) * TT + t0 + threadIdx.x;
        d_vt_h[o] = hh; d_vt_l[o] = ll;
    }
}

// ---------------- launch ----------------
template<typename T> static T* symaddr(const void* sym) {
    void* p = nullptr;
    cudaGetSymbolAddress(&p, sym);
    return (T*)p;
}

extern "C" void kernel_launch(void* const* d_in, const int* in_sizes, int n_in,
                              void* d_out, int out_size) {
    const float* x   = (const float*)d_in[0];
    const float* gq  = (const float*)d_in[1];
    const float* Wq  = (const float*)d_in[2];
    const float* bq  = (const float*)d_in[3];
    const float* gkv = (const float*)d_in[4];
    const float* Wkv = (const float*)d_in[5];
    const float* bkv = (const float*)d_in[6];
    const float* gh  = (const float*)d_in[7];
    const float* Wo  = (const float*)d_in[8];
    const float* bo  = (const float*)d_in[9];
    float* out = (float*)d_out;

    bf16* xn_h = symaddr<bf16>(d_xn_h);  bf16* xn_l = symaddr<bf16>(d_xn_l);
    bf16* wc_h = symaddr<bf16>(d_wc_h);  bf16* wc_l = symaddr<bf16>(d_wc_l);
    bf16* wo_h = symaddr<bf16>(d_wo_h);  bf16* wo_l = symaddr<bf16>(d_wo_l);
    float* qkvlin = symaddr<float>(d_qkvlin);
    bf16* wvt_h = symaddr<bf16>(d_wvt_h); bf16* wvt_l = symaddr<bf16>(d_wvt_l);

    cudaFuncSetAttribute(mma_gemm<false>, cudaFuncAttributeMaxDynamicSharedMemorySize, G_SMEM);
    cudaFuncSetAttribute(mma_gemm<true>,  cudaFuncAttributeMaxDynamicSharedMemorySize, G_SMEM);
    cudaFuncSetAttribute(flash_kernel,    cudaFuncAttributeMaxDynamicSharedMemorySize, SMEM_FLASH);

    // 1-2. weight transpose+split with gain fold
    wtransg_kernel<<<dim3(DD / 32, DD / 32), dim3(32, 8)>>>(Wq, gq, wc_h, wc_l, DD, 0);
    wtransg_kernel<<<dim3(2 * DD / 32, DD / 32), dim3(32, 8)>>>(Wkv, gkv, wc_h, wc_l, 2 * DD, DD);

    // 3. RMSNorm -> single hi/lo activation
    rmsnorm_kernel<<<ROWS, 256>>>(x);

    // 4. fused QKV projection: [4096,2048] x [6144,2048]^T  (ncu capture target)
    mma_gemm<false><<<dim3(NQKV / 128, ROWS / 64), 128, G_SMEM>>>(
        xn_h, xn_l, wc_h, wc_l, nullptr, qkvlin, DD, NQKV, 1.0f);

    // 5-6. per-head RMSNorm (+bias) and v transpose (+bias)
    head_rms_kernel<<<BB * HH * TT, HD>>>(gh, bq, bkv);
    vtrans_kernel<<<dim3(TT / 32, HD / 32, BB * HH), dim3(32, 8)>>>(bkv);

    // 7. fused flash attention -> d_wvt hi/lo
    flash_kernel<<<dim3(TT / 128, BB * HH), 256, SMEM_FLASH>>>();

    // 8. O weight transpose
    wtransg_kernel<<<dim3(DD / 32, DD / 32), dim3(32, 8)>>>(Wo, nullptr, wo_h, wo_l, DD, 0);

    // 9. out = wvt @ Wo^T + bo
    mma_gemm<true><<<dim3(DD / 128, ROWS / 64), 128, G_SMEM>>>(
        wvt_h, wvt_l, wo_h, wo_l, bo, out, DD, DD, 1.0f);
}

// round 13
// speedup vs baseline: 1.3775x; 1.3775x over previous
#include <cuda_runtime.h>
#include <cuda_fp16.h>
#include <cstdint>
#include <math.h>

#define BB 2
#define TT 2048
#define DD 2048
#define HH 16
#define HD 128
#define ROWS (BB*TT)              // 4096
#define NQKV (3*DD)               // 6144
#define EPSV 1.1920929e-07f
#define ATT_SCALE 0.088388347648318447f   // 1/sqrt(128)

typedef __half hf;

// ---------------- scratch (device globals) ----------------
__device__ __align__(256) hf d_xn  [ROWS*DD];                            // rms(x), hi only
__device__ __align__(256) hf d_wc_h[NQKV*DD], d_wc_l[NQKV*DD];           // [6144,K] gains folded
__device__ __align__(256) hf d_wo_h[DD*DD],   d_wo_l[DD*DD];             // [N,K]
__device__ __align__(256) float d_qkvlin[ROWS*NQKV];                     // [4096,6144]
__device__ __align__(256) hf d_qn  [BB*HH*TT*HD];                        // [B,H,T,d] hi only
__device__ __align__(256) hf d_kn_h[BB*HH*TT*HD], d_kn_l[BB*HH*TT*HD];   // [B,H,T,d]
__device__ __align__(256) hf d_vt_h[BB*HH*HD*TT], d_vt_l[BB*HH*HD*TT];   // [B,H,d,T]
__device__ __align__(256) hf d_wvt [ROWS*DD];                            // [B*T, D] hi only

// ---------------- helpers ----------------
__device__ __forceinline__ void split2h(float x, hf& h, hf& l) {
    h = __float2half(x);
    l = __float2half(x - __half2float(h));
}

__device__ __forceinline__ uint32_t pack_h2(hf a, hf b) {
    __half2 t = __halves2half2(a, b);
    return *(uint32_t*)&t;
}

__device__ __forceinline__ float blockReduceSum(float v, float* sh) {
    __syncthreads();
    int lane = threadIdx.x & 31, w = threadIdx.x >> 5;
    #pragma unroll
    for (int o = 16; o > 0; o >>= 1) v += __shfl_down_sync(0xffffffffu, v, o);
    if (lane == 0) sh[w] = v;
    __syncthreads();
    int nw = blockDim.x >> 5;
    v = (threadIdx.x < nw) ? sh[threadIdx.x] : 0.0f;
    if (w == 0) {
        #pragma unroll
        for (int o = 16; o > 0; o >>= 1) v += __shfl_down_sync(0xffffffffu, v, o);
        if (lane == 0) sh[0] = v;
    }
    __syncthreads();
    return sh[0];
}

__device__ __forceinline__ uint32_t smem_u32(const void* p) {
    return (uint32_t)__cvta_generic_to_shared(p);
}

__device__ __forceinline__ void ldsm4(uint32_t addr, uint32_t* r) {
    asm volatile("ldmatrix.sync.aligned.m8n8.x4.shared.b16 {%0,%1,%2,%3}, [%4];"
                 : "=r"(r[0]), "=r"(r[1]), "=r"(r[2]), "=r"(r[3]) : "r"(addr));
}

__device__ __forceinline__ void mma16816(float* c, const uint32_t* a, const uint32_t* b) {
    asm volatile("mma.sync.aligned.m16n8k16.row.col.f32.f16.f16.f32 "
                 "{%0,%1,%2,%3}, {%4,%5,%6,%7}, {%8,%9}, {%0,%1,%2,%3};"
                 : "+f"(c[0]), "+f"(c[1]), "+f"(c[2]), "+f"(c[3])
                 : "r"(a[0]), "r"(a[1]), "r"(a[2]), "r"(a[3]), "r"(b[0]), "r"(b[1]));
}

__device__ __forceinline__ void cpasync16(uint32_t dst, const void* src) {
    asm volatile("cp.async.cg.shared.global [%0], [%1], 16;" :: "r"(dst), "l"(src));
}
__device__ __forceinline__ void cpcommit() {
    asm volatile("cp.async.commit_group;" ::: "memory");
}
template<int N> __device__ __forceinline__ void cpwait() {
    asm volatile("cp.async.wait_group %0;" :: "n"(N) : "memory");
}

// ---------------- fp16x2 GEMM: 64x128 block, 128 threads (2x2 warps), 2 CTAs/SM ----
// C[M,N] = alpha*(A @ Bt^T)(+bias). A:[M,K] fp16 (hi only); Bt:[N,K] fp16 hi/lo.
// Per k16 product: 2 MMAs (ah*bh + ah*bl). K % 64 == 0.
// Per stage: A 8KB | Bh 16KB | Bl 16KB = 40KB. 2 stages = 80KB -> 2 CTAs/SM.
#define G_STAGE 40960
#define G_SMEM  (2*G_STAGE)
#define OFF_BH  8192
#define OFF_BL  24576

template<bool HAS_BIAS>
__global__ __launch_bounds__(128, 2)
void mma_gemm(const hf* __restrict__ A, const hf* __restrict__ Bh,
              const hf* __restrict__ Bl,
              const float* __restrict__ bias, float* __restrict__ C,
              int K, int ldc, float alpha) {
    extern __shared__ char smem[];
    const uint32_t sb = smem_u32(smem);
    const int tid = threadIdx.x, lane = tid & 31, w = tid >> 5;
    const int wm = w >> 1, wn = w & 1;          // warp grid 2(M) x 2(N)
    const int bm = blockIdx.y * 64, bn = blockIdx.x * 128;

    const hf* aSrc = A + (size_t)bm * K;
    const hf* bSrcs[2] = { Bh + (size_t)bn * K, Bl + (size_t)bn * K };

    float acc[2][8][4];
    #pragma unroll
    for (int t = 0; t < 2; t++)
        #pragma unroll
        for (int n = 0; n < 8; n++)
            #pragma unroll
            for (int r = 0; r < 4; r++) acc[t][n][r] = 0.0f;

    const int NC = K >> 6;

    auto issue_load = [&](int stage, int kc) {
        const uint32_t base = sb + stage * G_STAGE;
        const int k0 = kc << 6;
        {                                        // A: 64 rows x 8 cols of 16B
            const hf* sp = aSrc + k0;
            #pragma unroll
            for (int j = 0; j < 4; j++) {
                int f = tid + j * 128;
                int r = f >> 3, c = f & 7;
                cpasync16(base + (uint32_t)(r * 128 + ((c ^ (r & 7)) << 4)),
                          sp + (size_t)r * K + c * 8);
            }
        }
        #pragma unroll
        for (int t = 0; t < 2; t++) {            // B hi/lo: 128 rows x 8 cols of 16B
            const hf* sp = bSrcs[t] + k0;
            const uint32_t tb = base + OFF_BH + t * (OFF_BL - OFF_BH);
            #pragma unroll
            for (int j = 0; j < 8; j++) {
                int f = tid + j * 128;
                int r = f >> 3, c = f & 7;
                cpasync16(tb + (uint32_t)(r * 128 + ((c ^ (r & 7)) << 4)),
                          sp + (size_t)r * K + c * 8);
            }
        }
        cpcommit();
    };

    issue_load(0, 0);
    for (int kc = 0; kc < NC; kc++) {
        const int cur = kc & 1;
        if (kc + 1 < NC) { issue_load(cur ^ 1, kc + 1); cpwait<1>(); }
        else             { cpwait<0>(); }
        __syncthreads();

        const uint32_t baseA  = sb + cur * G_STAGE;
        const uint32_t baseBH = baseA + OFF_BH;
        const uint32_t baseBL = baseA + OFF_BL;
        #pragma unroll
        for (int s = 0; s < 4; s++) {
            uint32_t aH[2][4], bH[8][2], bL[8][2];
            #pragma unroll
            for (int t = 0; t < 2; t++) {
                int m = wm * 32 + t * 16 + (lane & 15);
                uint32_t off = (uint32_t)(m * 128 + (((s * 2 + (lane >> 4)) ^ (m & 7)) << 4));
                ldsm4(baseA + off, aH[t]);
            }
            #pragma unroll
            for (int u = 0; u < 4; u++) {
                int n = wn * 64 + u * 16 + (lane & 15);
                uint32_t off = (uint32_t)(n * 128 + (((s * 2 + (lane >> 4)) ^ (n & 7)) << 4));
                uint32_t r4[4];
                ldsm4(baseBH + off, r4);
                bH[2*u][0] = r4[0]; bH[2*u+1][0] = r4[1];
                bH[2*u][1] = r4[2]; bH[2*u+1][1] = r4[3];
                ldsm4(baseBL + off, r4);
                bL[2*u][0] = r4[0]; bL[2*u+1][0] = r4[1];
                bL[2*u][1] = r4[2]; bL[2*u+1][1] = r4[3];
            }
            #pragma unroll
            for (int t = 0; t < 2; t++)
                #pragma unroll
                for (int n = 0; n < 8; n++) {
                    mma16816(acc[t][n], aH[t], bH[n]);
                    mma16816(acc[t][n], aH[t], bL[n]);
                }
        }
        __syncthreads();
    }

    #pragma unroll
    for (int t = 0; t < 2; t++) {
        #pragma unroll
        for (int n = 0; n < 8; n++) {
            int m0 = bm + wm * 32 + t * 16 + (lane >> 2);
            int n0 = bn + wn * 64 + n * 8 + 2 * (lane & 3);
            float bx = 0.0f, by = 0.0f;
            if (HAS_BIAS) { bx = bias[n0]; by = bias[n0 + 1]; }
            float2 v0 = { acc[t][n][0] * alpha + bx, acc[t][n][1] * alpha + by };
            float2 v1 = { acc[t][n][2] * alpha + bx, acc[t][n][3] * alpha + by };
            *(float2*)(C + (size_t)m0 * ldc + n0) = v0;
            *(float2*)(C + (size_t)(m0 + 8) * ldc + n0) = v1;
        }
    }
}

// ---------------- fused flash attention (fp16x2: Q,P hi only; K,V hi/lo) ----------
#define FSEG 32768
#define SMEM_FLASH (5*FSEG)                 // Kh | Kl | Vh | Vl | Qh

__device__ __forceinline__ uint32_t swz(int r, int c) {
    return (uint32_t)(r * 256 + (((c & 8) | ((c ^ r) & 7)) << 4));
}

__global__ __launch_bounds__(256, 1)
void flash_kernel() {
    extern __shared__ char smem[];
    const uint32_t sb = smem_u32(smem);
    const uint32_t sKh = sb, sKl = sb + FSEG, sVh = sb + 2*FSEG, sVl = sb + 3*FSEG;
    const uint32_t sQh = sb + 4*FSEG;

    const int tid = threadIdx.x, lane = tid & 31, w = tid >> 5;
    const int bh = blockIdx.y;
    const int q0 = blockIdx.x * 128;

    const hf* qh = d_qn + (size_t)bh * TT * HD + (size_t)q0 * HD;
    const hf* kh = d_kn_h + (size_t)bh * TT * HD;
    const hf* kl = d_kn_l + (size_t)bh * TT * HD;
    const hf* vh = d_vt_h + (size_t)bh * HD * TT;
    const hf* vl = d_vt_l + (size_t)bh * HD * TT;

    auto loadT = [&](uint32_t dstb, const hf* src, int rowStride) {
        #pragma unroll
        for (int j = 0; j < 8; j++) {
            int f = tid + j * 256;
            int r = f >> 4, c = f & 15;
            cpasync16(dstb + swz(r, c), src + (size_t)r * rowStride + c * 8);
        }
    };

    loadT(sQh, qh, HD);
    loadT(sKh, kh, HD); loadT(sKl, kl, HD);
    loadT(sVh, vh, TT); loadT(sVl, vl, TT);
    cpcommit();
    cpwait<0>();
    __syncthreads();

    float o[16][4];
    #pragma unroll
    for (int f = 0; f < 16; f++)
        #pragma unroll
        for (int j = 0; j < 4; j++) o[f][j] = 0.0f;
    float mrow[2] = {-INFINITY, -INFINITY};
    float lrow[2] = {0.0f, 0.0f};

    const int NT = TT / 128;
    for (int i = 0; i < NT; i++) {
        float sacc[16][4];
        #pragma unroll
        for (int f = 0; f < 16; f++)
            #pragma unroll
            for (int j = 0; j < 4; j++) sacc[f][j] = 0.0f;

        #pragma unroll
        for (int s = 0; s < 8; s++) {
            const int mR = (w << 4) + (lane & 15);
            const int cc = 2 * s + (lane >> 4);
            uint32_t aH[4];
            ldsm4(sQh + swz(mR, cc), aH);
            #pragma unroll
            for (int u = 0; u < 8; u++) {
                const int n = u * 16 + (lane & 15);
                uint32_t r4h[4], r4l[4];
                ldsm4(sKh + swz(n, cc), r4h);
                ldsm4(sKl + swz(n, cc), r4l);
                uint32_t b0h[2] = {r4h[0], r4h[2]}, b1h[2] = {r4h[1], r4h[3]};
                uint32_t b0l[2] = {r4l[0], r4l[2]}, b1l[2] = {r4l[1], r4l[3]};
                mma16816(sacc[2*u],   aH, b0h);
                mma16816(sacc[2*u],   aH, b0l);
                mma16816(sacc[2*u+1], aH, b1h);
                mma16816(sacc[2*u+1], aH, b1l);
            }
        }
        __syncthreads();
        if (i + 1 < NT) { loadT(sKh, kh + (size_t)(i+1)*128*HD, HD);
                          loadT(sKl, kl + (size_t)(i+1)*128*HD, HD); cpcommit(); }

        float mnew[2] = {mrow[0], mrow[1]};
        #pragma unroll
        for (int f = 0; f < 16; f++) {
            mnew[0] = fmaxf(mnew[0], fmaxf(sacc[f][0], sacc[f][1]));
            mnew[1] = fmaxf(mnew[1], fmaxf(sacc[f][2], sacc[f][3]));
        }
        #pragma unroll
        for (int rr = 0; rr < 2; rr++) {
            mnew[rr] = fmaxf(mnew[rr], __shfl_xor_sync(0xffffffffu, mnew[rr], 1));
            mnew[rr] = fmaxf(mnew[rr], __shfl_xor_sync(0xffffffffu, mnew[rr], 2));
        }
        float resc[2] = { __expf(mrow[0] - mnew[0]), __expf(mrow[1] - mnew[1]) };
        mrow[0] = mnew[0]; mrow[1] = mnew[1];
        float psum[2] = {0.0f, 0.0f};
        #pragma unroll
        for (int f = 0; f < 16; f++) {
            sacc[f][0] = __expf(sacc[f][0] - mrow[0]);
            sacc[f][1] = __expf(sacc[f][1] - mrow[0]);
            sacc[f][2] = __expf(sacc[f][2] - mrow[1]);
            sacc[f][3] = __expf(sacc[f][3] - mrow[1]);
            psum[0] += sacc[f][0] + sacc[f][1];
            psum[1] += sacc[f][2] + sacc[f][3];
        }
        #pragma unroll
        for (int rr = 0; rr < 2; rr++) {
            psum[rr] += __shfl_xor_sync(0xffffffffu, psum[rr], 1);
            psum[rr] += __shfl_xor_sync(0xffffffffu, psum[rr], 2);
        }
        lrow[0] = lrow[0] * resc[0] + psum[0];
        lrow[1] = lrow[1] * resc[1] + psum[1];
        #pragma unroll
        for (int f = 0; f < 16; f++) {
            o[f][0] *= resc[0]; o[f][1] *= resc[0];
            o[f][2] *= resc[1]; o[f][3] *= resc[1];
        }

        if (i > 0) {
            if (i + 1 < NT) cpwait<1>(); else cpwait<0>();
            __syncthreads();
        }

        #pragma unroll
        for (int s = 0; s < 8; s++) {
            const int f0 = 2 * s, f1 = 2 * s + 1;
            uint32_t aPh[4];
            aPh[0] = pack_h2(__float2half(sacc[f0][0]), __float2half(sacc[f0][1]));
            aPh[1] = pack_h2(__float2half(sacc[f0][2]), __float2half(sacc[f0][3]));
            aPh[2] = pack_h2(__float2half(sacc[f1][0]), __float2half(sacc[f1][1]));
            aPh[3] = pack_h2(__float2half(sacc[f1][2]), __float2half(sacc[f1][3]));
            const int cc = 2 * s + (lane >> 4);
            #pragma unroll
            for (int u = 0; u < 8; u++) {
                const int n = u * 16 + (lane & 15);
                uint32_t r4h[4], r4l[4];
                ldsm4(sVh + swz(n, cc), r4h);
                ldsm4(sVl + swz(n, cc), r4l);
                uint32_t b0h[2] = {r4h[0], r4h[2]}, b1h[2] = {r4h[1], r4h[3]};
                uint32_t b0l[2] = {r4l[0], r4l[2]}, b1l[2] = {r4l[1], r4l[3]};
                mma16816(o[2*u],   aPh, b0h);
                mma16816(o[2*u],   aPh, b0l);
                mma16816(o[2*u+1], aPh, b1h);
                mma16816(o[2*u+1], aPh, b1l);
            }
        }
        __syncthreads();
        if (i + 1 < NT) {
            loadT(sVh, vh + (size_t)(i+1)*128, TT);
            loadT(sVl, vl + (size_t)(i+1)*128, TT);
            cpcommit();
            cpwait<1>();
            __syncthreads();
        }
    }

    // epilogue: O /= l, write d_wvt (hi only) in [B*T, D]
    const int b = bh >> 4, h = bh & 15;
    const float inv0 = 1.0f / lrow[0], inv1 = 1.0f / lrow[1];
    const int r0 = (w << 4) + (lane >> 2);
    const size_t bt0 = (size_t)(b * TT + q0 + r0) * DD;
    const size_t bt1 = (size_t)(b * TT + q0 + r0 + 8) * DD;
    const int colb = h * HD + 2 * (lane & 3);
    #pragma unroll
    for (int f = 0; f < 16; f++) {
        const int col = colb + f * 8;
        *(uint32_t*)(d_wvt + bt0 + col) =
            pack_h2(__float2half(o[f][0] * inv0), __float2half(o[f][1] * inv0));
        *(uint32_t*)(d_wvt + bt1 + col) =
            pack_h2(__float2half(o[f][2] * inv1), __float2half(o[f][3] * inv1));
    }
}

// ---------------- elementwise producers ----------------
__global__ void rmsnorm_kernel(const float* __restrict__ x) {
    int row = blockIdx.x;
    const float* xr = x + (size_t)row * DD;
    float s = 0.0f;
    for (int c = threadIdx.x; c < DD; c += blockDim.x) { float v = xr[c]; s += v * v; }
    __shared__ float sh[32];
    s = blockReduceSum(s, sh);
    float inv = rsqrtf(s * (1.0f / DD) + EPSV);
    for (int c = threadIdx.x; c < DD; c += blockDim.x) {
        d_xn[(size_t)row * DD + c] = __float2half(xr[c] * inv);
    }
}

// W[K,Nd] fp32 -> dest[(rowOff+n), k] hi/lo fp16 with optional per-k gain fold
__global__ void wtransg_kernel(const float* __restrict__ W, const float* __restrict__ g,
                               hf* __restrict__ Th, hf* __restrict__ Tl,
                               int Nd, int rowOff) {
    __shared__ float tile[32][33];
    int k0 = blockIdx.y * 32, n0 = blockIdx.x * 32;
    for (int j = threadIdx.y; j < 32; j += 8)
        tile[j][threadIdx.x] = W[(size_t)(k0 + j) * Nd + n0 + threadIdx.x];
    __syncthreads();
    float gv = g ? g[k0 + threadIdx.x] : 1.0f;
    for (int j = threadIdx.y; j < 32; j += 8) {
        float v = tile[threadIdx.x][j] * gv;
        hf h, l; split2h(v, h, l);
        size_t o = (size_t)(rowOff + n0 + j) * DD + k0 + threadIdx.x;
        Th[o] = h; Tl[o] = l;
    }
}

__global__ void head_rms_kernel(const float* __restrict__ ghead,
                                const float* __restrict__ bq,
                                const float* __restrict__ bkv) {
    int bid = blockIdx.x;
    int t = bid & (TT - 1);
    int bh = bid / TT;
    int h = bh & (HH - 1);
    int b = bh / HH;
    int bt = b * TT + t;
    int i = threadIdx.x;
    int col = h * HD + i;

    float qv = d_qkvlin[(size_t)bt * NQKV + col] + bq[col];
    float kv = d_qkvlin[(size_t)bt * NQKV + DD + col] + bkv[col];

    __shared__ float sh[32];
    float sq = blockReduceSum(qv * qv, sh);
    float sk = blockReduceSum(kv * kv, sh);

    float g = ghead[i];
    size_t o = (size_t)bid * HD + i;
    float qn = qv * rsqrtf(sq * (1.0f / HD) + EPSV) * g * ATT_SCALE;
    float kn = kv * rsqrtf(sk * (1.0f / HD) + EPSV) * g;
    d_qn[o] = __float2half(qn);
    hf hh, ll;
    split2h(kn, hh, ll); d_kn_h[o] = hh; d_kn_l[o] = ll;
}

__global__ void vtrans_kernel(const float* __restrict__ bkv) {
    __shared__ float tile[32][33];
    int bh = blockIdx.z;
    int b = bh >> 4, h = bh & 15;
    int t0 = blockIdx.x * 32, i0 = blockIdx.y * 32;
    for (int j = threadIdx.y; j < 32; j += 8)
        tile[j][threadIdx.x] =
            d_qkvlin[(size_t)(b * TT + t0 + j) * NQKV + 2 * DD + h * HD + i0 + threadIdx.x];
    __syncthreads();
    for (int j = threadIdx.y; j < 32; j += 8) {
        float v = tile[threadIdx.x][j] + bkv[DD + h * HD + i0 + j];
        hf hh, ll; split2h(v, hh, ll);
        size_t o = ((size_t)bh * HD + i0 + j) * TT + t0 + threadIdx.x;
        d_vt_h[o] = hh; d_vt_l[o] = ll;
    }
}

// ---------------- launch ----------------
template<typename T> static T* symaddr(const void* sym) {
    void* p = nullptr;
    cudaGetSymbolAddress(&p, sym);
    return (T*)p;
}

extern "C" void kernel_launch(void* const* d_in, const int* in_sizes, int n_in,
                              void* d_out, int out_size) {
    const float* x   = (const float*)d_in[0];
    const float* gq  = (const float*)d_in[1];
    const float* Wq  = (const float*)d_in[2];
    const float* bq  = (const float*)d_in[3];
    const float* gkv = (const float*)d_in[4];
    const float* Wkv = (const float*)d_in[5];
    const float* bkv = (const float*)d_in[6];
    const float* gh  = (const float*)d_in[7];
    const float* Wo  = (const float*)d_in[8];
    const float* bo  = (const float*)d_in[9];
    float* out = (float*)d_out;

    hf* xn   = symaddr<hf>(d_xn);
    hf* wc_h = symaddr<hf>(d_wc_h);  hf* wc_l = symaddr<hf>(d_wc_l);
    hf* wo_h = symaddr<hf>(d_wo_h);  hf* wo_l = symaddr<hf>(d_wo_l);
    float* qkvlin = symaddr<float>(d_qkvlin);
    hf* wvt  = symaddr<hf>(d_wvt);

    cudaFuncSetAttribute(mma_gemm<false>, cudaFuncAttributeMaxDynamicSharedMemorySize, G_SMEM);
    cudaFuncSetAttribute(mma_gemm<true>,  cudaFuncAttributeMaxDynamicSharedMemorySize, G_SMEM);
    cudaFuncSetAttribute(flash_kernel,    cudaFuncAttributeMaxDynamicSharedMemorySize, SMEM_FLASH);

    // 1-2. weight transpose+split with gain fold
    wtransg_kernel<<<dim3(DD / 32, DD / 32), dim3(32, 8)>>>(Wq, gq, wc_h, wc_l, DD, 0);
    wtransg_kernel<<<dim3(2 * DD / 32, DD / 32), dim3(32, 8)>>>(Wkv, gkv, wc_h, wc_l, 2 * DD, DD);

    // 3. RMSNorm -> fp16 activation (hi only)
    rmsnorm_kernel<<<ROWS, 256>>>(x);

    // 4. fused QKV projection: [4096,2048] x [6144,2048]^T  (ncu capture target)
    mma_gemm<false><<<dim3(NQKV / 128, ROWS / 64), 128, G_SMEM>>>(
        xn, wc_h, wc_l, nullptr, qkvlin, DD, NQKV, 1.0f);

    // 5-6. per-head RMSNorm (+bias) and v transpose (+bias)
    head_rms_kernel<<<BB * HH * TT, HD>>>(gh, bq, bkv);
    vtrans_kernel<<<dim3(TT / 32, HD / 32, BB * HH), dim3(32, 8)>>>(bkv);

    // 7. fused flash attention -> d_wvt (hi only)
    flash_kernel<<<dim3(TT / 128, BB * HH), 256, SMEM_FLASH>>>();

    // 8. O weight transpose
    wtransg_kernel<<<dim3(DD / 32, DD / 32), dim3(32, 8)>>>(Wo, nullptr, wo_h, wo_l, DD, 0);

    // 9. out = wvt @ Wo^T + bo
    mma_gemm<true><<<dim3(DD / 128, ROWS / 64), 128, G_SMEM>>>(
        wvt, wo_h, wo_l, bo, out, DD, DD, 1.0f);
}

// round 15
// speedup vs baseline: 1.6331x; 1.1855x over previous
#include <cuda_runtime.h>
#include <cuda_fp16.h>
#include <cstdint>
#include <math.h>

#define BB 2
#define TT 2048
#define DD 2048
#define HH 16
#define HD 128
#define ROWS (BB*TT)              // 4096
#define NQKV (3*DD)               // 6144
#define EPSV 1.1920929e-07f
#define ATT_SCALE 0.088388347648318447f   // 1/sqrt(128)

typedef __half hf;

// ---------------- scratch (device globals) ----------------
__device__ __align__(256) hf d_xn  [ROWS*DD];                            // rms(x), hi only
__device__ __align__(256) hf d_wc_h[NQKV*DD], d_wc_l[NQKV*DD];           // [6144,K] gains folded
__device__ __align__(256) hf d_wo_h[DD*DD],   d_wo_l[DD*DD];             // [N,K]
__device__ __align__(256) float d_qkvlin[ROWS*NQKV];                     // [4096,6144]
__device__ __align__(256) hf d_qn  [BB*HH*TT*HD];                        // [B,H,T,d] hi only
__device__ __align__(256) hf d_kn  [BB*HH*TT*HD];                        // [B,H,T,d] hi only
__device__ __align__(256) hf d_vt  [BB*HH*HD*TT];                        // [B,H,d,T] hi only
__device__ __align__(256) hf d_wvt [ROWS*DD];                            // [B*T, D] hi only

// ---------------- helpers ----------------
__device__ __forceinline__ void split2h(float x, hf& h, hf& l) {
    h = __float2half(x);
    l = __float2half(x - __half2float(h));
}

__device__ __forceinline__ uint32_t pack_h2(hf a, hf b) {
    __half2 t = __halves2half2(a, b);
    return *(uint32_t*)&t;
}

__device__ __forceinline__ float blockReduceSum(float v, float* sh) {
    __syncthreads();
    int lane = threadIdx.x & 31, w = threadIdx.x >> 5;
    #pragma unroll
    for (int o = 16; o > 0; o >>= 1) v += __shfl_down_sync(0xffffffffu, v, o);
    if (lane == 0) sh[w] = v;
    __syncthreads();
    int nw = blockDim.x >> 5;
    v = (threadIdx.x < nw) ? sh[threadIdx.x] : 0.0f;
    if (w == 0) {
        #pragma unroll
        for (int o = 16; o > 0; o >>= 1) v += __shfl_down_sync(0xffffffffu, v, o);
        if (lane == 0) sh[0] = v;
    }
    __syncthreads();
    return sh[0];
}

__device__ __forceinline__ uint32_t smem_u32(const void* p) {
    return (uint32_t)__cvta_generic_to_shared(p);
}

__device__ __forceinline__ void ldsm4(uint32_t addr, uint32_t* r) {
    asm volatile("ldmatrix.sync.aligned.m8n8.x4.shared.b16 {%0,%1,%2,%3}, [%4];"
                 : "=r"(r[0]), "=r"(r[1]), "=r"(r[2]), "=r"(r[3]) : "r"(addr));
}

__device__ __forceinline__ void mma16816(float* c, const uint32_t* a, const uint32_t* b) {
    asm volatile("mma.sync.aligned.m16n8k16.row.col.f32.f16.f16.f32 "
                 "{%0,%1,%2,%3}, {%4,%5,%6,%7}, {%8,%9}, {%0,%1,%2,%3};"
                 : "+f"(c[0]), "+f"(c[1]), "+f"(c[2]), "+f"(c[3])
                 : "r"(a[0]), "r"(a[1]), "r"(a[2]), "r"(a[3]), "r"(b[0]), "r"(b[1]));
}

__device__ __forceinline__ void cpasync16(uint32_t dst, const void* src) {
    asm volatile("cp.async.cg.shared.global [%0], [%1], 16;" :: "r"(dst), "l"(src));
}
__device__ __forceinline__ void cpcommit() {
    asm volatile("cp.async.commit_group;" ::: "memory");
}
template<int N> __device__ __forceinline__ void cpwait() {
    asm volatile("cp.async.wait_group %0;" :: "n"(N) : "memory");
}

// ---------------- fp16x2 GEMM (unchanged from round 13) ----------------
// C[M,N] = alpha*(A @ Bt^T)(+bias). A:[M,K] fp16 (hi only); Bt:[N,K] fp16 hi/lo.
// Per k16 product: 2 MMAs (ah*bh + ah*bl). K % 64 == 0.
// Per stage: A 8KB | Bh 16KB | Bl 16KB = 40KB. 2 stages = 80KB -> 2 CTAs/SM.
#define G_STAGE 40960
#define G_SMEM  (2*G_STAGE)
#define OFF_BH  8192
#define OFF_BL  24576

template<bool HAS_BIAS>
__global__ __launch_bounds__(128, 2)
void mma_gemm(const hf* __restrict__ A, const hf* __restrict__ Bh,
              const hf* __restrict__ Bl,
              const float* __restrict__ bias, float* __restrict__ C,
              int K, int ldc, float alpha) {
    extern __shared__ char smem[];
    const uint32_t sb = smem_u32(smem);
    const int tid = threadIdx.x, lane = tid & 31, w = tid >> 5;
    const int wm = w >> 1, wn = w & 1;          // warp grid 2(M) x 2(N)
    const int bm = blockIdx.y * 64, bn = blockIdx.x * 128;

    const hf* aSrc = A + (size_t)bm * K;
    const hf* bSrcs[2] = { Bh + (size_t)bn * K, Bl + (size_t)bn * K };

    float acc[2][8][4];
    #pragma unroll
    for (int t = 0; t < 2; t++)
        #pragma unroll
        for (int n = 0; n < 8; n++)
            #pragma unroll
            for (int r = 0; r < 4; r++) acc[t][n][r] = 0.0f;

    const int NC = K >> 6;

    auto issue_load = [&](int stage, int kc) {
        const uint32_t base = sb + stage * G_STAGE;
        const int k0 = kc << 6;
        {                                        // A: 64 rows x 8 cols of 16B
            const hf* sp = aSrc + k0;
            #pragma unroll
            for (int j = 0; j < 4; j++) {
                int f = tid + j * 128;
                int r = f >> 3, c = f & 7;
                cpasync16(base + (uint32_t)(r * 128 + ((c ^ (r & 7)) << 4)),
                          sp + (size_t)r * K + c * 8);
            }
        }
        #pragma unroll
        for (int t = 0; t < 2; t++) {            // B hi/lo: 128 rows x 8 cols of 16B
            const hf* sp = bSrcs[t] + k0;
            const uint32_t tb = base + OFF_BH + t * (OFF_BL - OFF_BH);
            #pragma unroll
            for (int j = 0; j < 8; j++) {
                int f = tid + j * 128;
                int r = f >> 3, c = f & 7;
                cpasync16(tb + (uint32_t)(r * 128 + ((c ^ (r & 7)) << 4)),
                          sp + (size_t)r * K + c * 8);
            }
        }
        cpcommit();
    };

    issue_load(0, 0);
    for (int kc = 0; kc < NC; kc++) {
        const int cur = kc & 1;
        if (kc + 1 < NC) { issue_load(cur ^ 1, kc + 1); cpwait<1>(); }
        else             { cpwait<0>(); }
        __syncthreads();

        const uint32_t baseA  = sb + cur * G_STAGE;
        const uint32_t baseBH = baseA + OFF_BH;
        const uint32_t baseBL = baseA + OFF_BL;
        #pragma unroll
        for (int s = 0; s < 4; s++) {
            uint32_t aH[2][4], bH[8][2], bL[8][2];
            #pragma unroll
            for (int t = 0; t < 2; t++) {
                int m = wm * 32 + t * 16 + (lane & 15);
                uint32_t off = (uint32_t)(m * 128 + (((s * 2 + (lane >> 4)) ^ (m & 7)) << 4));
                ldsm4(baseA + off, aH[t]);
            }
            #pragma unroll
            for (int u = 0; u < 4; u++) {
                int n = wn * 64 + u * 16 + (lane & 15);
                uint32_t off = (uint32_t)(n * 128 + (((s * 2 + (lane >> 4)) ^ (n & 7)) << 4));
                uint32_t r4[4];
                ldsm4(baseBH + off, r4);
                bH[2*u][0] = r4[0]; bH[2*u+1][0] = r4[1];
                bH[2*u][1] = r4[2]; bH[2*u+1][1] = r4[3];
                ldsm4(baseBL + off, r4);
                bL[2*u][0] = r4[0]; bL[2*u+1][0] = r4[1];
                bL[2*u][1] = r4[2]; bL[2*u+1][1] = r4[3];
            }
            #pragma unroll
            for (int t = 0; t < 2; t++)
                #pragma unroll
                for (int n = 0; n < 8; n++) {
                    mma16816(acc[t][n], aH[t], bH[n]);
                    mma16816(acc[t][n], aH[t], bL[n]);
                }
        }
        __syncthreads();
    }

    #pragma unroll
    for (int t = 0; t < 2; t++) {
        #pragma unroll
        for (int n = 0; n < 8; n++) {
            int m0 = bm + wm * 32 + t * 16 + (lane >> 2);
            int n0 = bn + wn * 64 + n * 8 + 2 * (lane & 3);
            float bx = 0.0f, by = 0.0f;
            if (HAS_BIAS) { bx = bias[n0]; by = bias[n0 + 1]; }
            float2 v0 = { acc[t][n][0] * alpha + bx, acc[t][n][1] * alpha + by };
            float2 v1 = { acc[t][n][2] * alpha + bx, acc[t][n][3] * alpha + by };
            *(float2*)(C + (size_t)m0 * ldc + n0) = v0;
            *(float2*)(C + (size_t)(m0 + 8) * ldc + n0) = v1;
        }
    }
}

// ---------------- fused flash attention (all-hi fp16: Q, K, V, P) ----------
#define FSEG 32768
#define SMEM_FLASH (3*FSEG)                 // Kh | Vh | Qh

__device__ __forceinline__ uint32_t swz(int r, int c) {
    return (uint32_t)(r * 256 + (((c & 8) | ((c ^ r) & 7)) << 4));
}

__global__ __launch_bounds__(256, 1)
void flash_kernel() {
    extern __shared__ char smem[];
    const uint32_t sb = smem_u32(smem);
    const uint32_t sKh = sb, sVh = sb + FSEG, sQh = sb + 2*FSEG;

    const int tid = threadIdx.x, lane = tid & 31, w = tid >> 5;
    const int bh = blockIdx.y;
    const int q0 = blockIdx.x * 128;

    const hf* qh = d_qn + (size_t)bh * TT * HD + (size_t)q0 * HD;
    const hf* kh = d_kn + (size_t)bh * TT * HD;
    const hf* vh = d_vt + (size_t)bh * HD * TT;

    auto loadT = [&](uint32_t dstb, const hf* src, int rowStride) {
        #pragma unroll
        for (int j = 0; j < 8; j++) {
            int f = tid + j * 256;
            int r = f >> 4, c = f & 15;
            cpasync16(dstb + swz(r, c), src + (size_t)r * rowStride + c * 8);
        }
    };

    loadT(sQh, qh, HD);
    loadT(sKh, kh, HD);
    loadT(sVh, vh, TT);
    cpcommit();
    cpwait<0>();
    __syncthreads();

    float o[16][4];
    #pragma unroll
    for (int f = 0; f < 16; f++)
        #pragma unroll
        for (int j = 0; j < 4; j++) o[f][j] = 0.0f;
    float mrow[2] = {-INFINITY, -INFINITY};
    float lrow[2] = {0.0f, 0.0f};

    const int NT = TT / 128;
    for (int i = 0; i < NT; i++) {
        // ---- S = Q @ K(i)^T ----
        float sacc[16][4];
        #pragma unroll
        for (int f = 0; f < 16; f++)
            #pragma unroll
            for (int j = 0; j < 4; j++) sacc[f][j] = 0.0f;

        #pragma unroll
        for (int s = 0; s < 8; s++) {
            const int mR = (w << 4) + (lane & 15);
            const int cc = 2 * s + (lane >> 4);
            uint32_t aH[4];
            ldsm4(sQh + swz(mR, cc), aH);
            #pragma unroll
            for (int u = 0; u < 8; u++) {
                const int n = u * 16 + (lane & 15);
                uint32_t r4h[4];
                ldsm4(sKh + swz(n, cc), r4h);
                uint32_t b0h[2] = {r4h[0], r4h[2]}, b1h[2] = {r4h[1], r4h[3]};
                mma16816(sacc[2*u],   aH, b0h);
                mma16816(sacc[2*u+1], aH, b1h);
            }
        }
        __syncthreads();                        // everyone done reading K(i)
        if (i + 1 < NT) { loadT(sKh, kh + (size_t)(i+1)*128*HD, HD); cpcommit(); }

        // ---- online softmax ----
        float mnew[2] = {mrow[0], mrow[1]};
        #pragma unroll
        for (int f = 0; f < 16; f++) {
            mnew[0] = fmaxf(mnew[0], fmaxf(sacc[f][0], sacc[f][1]));
            mnew[1] = fmaxf(mnew[1], fmaxf(sacc[f][2], sacc[f][3]));
        }
        #pragma unroll
        for (int rr = 0; rr < 2; rr++) {
            mnew[rr] = fmaxf(mnew[rr], __shfl_xor_sync(0xffffffffu, mnew[rr], 1));
            mnew[rr] = fmaxf(mnew[rr], __shfl_xor_sync(0xffffffffu, mnew[rr], 2));
        }
        float resc[2] = { __expf(mrow[0] - mnew[0]), __expf(mrow[1] - mnew[1]) };
        mrow[0] = mnew[0]; mrow[1] = mnew[1];
        float psum[2] = {0.0f, 0.0f};
        #pragma unroll
        for (int f = 0; f < 16; f++) {
            sacc[f][0] = __expf(sacc[f][0] - mrow[0]);
            sacc[f][1] = __expf(sacc[f][1] - mrow[0]);
            sacc[f][2] = __expf(sacc[f][2] - mrow[1]);
            sacc[f][3] = __expf(sacc[f][3] - mrow[1]);
            psum[0] += sacc[f][0] + sacc[f][1];
            psum[1] += sacc[f][2] + sacc[f][3];
        }
        #pragma unroll
        for (int rr = 0; rr < 2; rr++) {
            psum[rr] += __shfl_xor_sync(0xffffffffu, psum[rr], 1);
            psum[rr] += __shfl_xor_sync(0xffffffffu, psum[rr], 2);
        }
        lrow[0] = lrow[0] * resc[0] + psum[0];
        lrow[1] = lrow[1] * resc[1] + psum[1];
        #pragma unroll
        for (int f = 0; f < 16; f++) {
            o[f][0] *= resc[0]; o[f][1] *= resc[0];
            o[f][2] *= resc[1]; o[f][3] *= resc[1];
        }

        // V(i) visibility: for i>0 it was committed last iteration; drain to it.
        if (i > 0) {
            if (i + 1 < NT) cpwait<1>(); else cpwait<0>();
            __syncthreads();
        }

        // ---- O += P @ V(i) ----
        #pragma unroll
        for (int s = 0; s < 8; s++) {
            const int f0 = 2 * s, f1 = 2 * s + 1;
            uint32_t aPh[4];
            aPh[0] = pack_h2(__float2half(sacc[f0][0]), __float2half(sacc[f0][1]));
            aPh[1] = pack_h2(__float2half(sacc[f0][2]), __float2half(sacc[f0][3]));
            aPh[2] = pack_h2(__float2half(sacc[f1][0]), __float2half(sacc[f1][1]));
            aPh[3] = pack_h2(__float2half(sacc[f1][2]), __float2half(sacc[f1][3]));
            const int cc = 2 * s + (lane >> 4);
            #pragma unroll
            for (int u = 0; u < 8; u++) {
                const int n = u * 16 + (lane & 15);
                uint32_t r4h[4];
                ldsm4(sVh + swz(n, cc), r4h);
                uint32_t b0h[2] = {r4h[0], r4h[2]}, b1h[2] = {r4h[1], r4h[3]};
                mma16816(o[2*u],   aPh, b0h);
                mma16816(o[2*u+1], aPh, b1h);
            }
        }
        __syncthreads();                        // everyone done reading V(i)
        if (i + 1 < NT) {
            loadT(sVh, vh + (size_t)(i+1)*128, TT);
            cpcommit();
            cpwait<1>();                        // K(i+1) arrived (V(i+1) still in flight)
            __syncthreads();
        }
    }

    // epilogue: O /= l, write d_wvt (hi only) in [B*T, D]
    const int b = bh >> 4, h = bh & 15;
    const float inv0 = 1.0f / lrow[0], inv1 = 1.0f / lrow[1];
    const int r0 = (w << 4) + (lane >> 2);
    const size_t bt0 = (size_t)(b * TT + q0 + r0) * DD;
    const size_t bt1 = (size_t)(b * TT + q0 + r0 + 8) * DD;
    const int colb = h * HD + 2 * (lane & 3);
    #pragma unroll
    for (int f = 0; f < 16; f++) {
        const int col = colb + f * 8;
        *(uint32_t*)(d_wvt + bt0 + col) =
            pack_h2(__float2half(o[f][0] * inv0), __float2half(o[f][1] * inv0));
        *(uint32_t*)(d_wvt + bt1 + col) =
            pack_h2(__float2half(o[f][2] * inv1), __float2half(o[f][3] * inv1));
    }
}

// ---------------- elementwise producers ----------------
__global__ void rmsnorm_kernel(const float* __restrict__ x) {
    int row = blockIdx.x;
    const float* xr = x + (size_t)row * DD;
    float s = 0.0f;
    for (int c = threadIdx.x; c < DD; c += blockDim.x) { float v = xr[c]; s += v * v; }
    __shared__ float sh[32];
    s = blockReduceSum(s, sh);
    float inv = rsqrtf(s * (1.0f / DD) + EPSV);
    for (int c = threadIdx.x; c < DD; c += blockDim.x) {
        d_xn[(size_t)row * DD + c] = __float2half(xr[c] * inv);
    }
}

// W[K,Nd] fp32 -> dest[(rowOff+n), k] hi/lo fp16 with optional per-k gain fold
__global__ void wtransg_kernel(const float* __restrict__ W, const float* __restrict__ g,
                               hf* __restrict__ Th, hf* __restrict__ Tl,
                               int Nd, int rowOff) {
    __shared__ float tile[32][33];
    int k0 = blockIdx.y * 32, n0 = blockIdx.x * 32;
    for (int j = threadIdx.y; j < 32; j += 8)
        tile[j][threadIdx.x] = W[(size_t)(k0 + j) * Nd + n0 + threadIdx.x];
    __syncthreads();
    float gv = g ? g[k0 + threadIdx.x] : 1.0f;
    for (int j = threadIdx.y; j < 32; j += 8) {
        float v = tile[threadIdx.x][j] * gv;
        hf h, l; split2h(v, h, l);
        size_t o = (size_t)(rowOff + n0 + j) * DD + k0 + threadIdx.x;
        Th[o] = h; Tl[o] = l;
    }
}

__global__ void head_rms_kernel(const float* __restrict__ ghead,
                                const float* __restrict__ bq,
                                const float* __restrict__ bkv) {
    int bid = blockIdx.x;
    int t = bid & (TT - 1);
    int bh = bid / TT;
    int h = bh & (HH - 1);
    int b = bh / HH;
    int bt = b * TT + t;
    int i = threadIdx.x;
    int col = h * HD + i;

    float qv = d_qkvlin[(size_t)bt * NQKV + col] + bq[col];
    float kv = d_qkvlin[(size_t)bt * NQKV + DD + col] + bkv[col];

    __shared__ float sh[32];
    float sq = blockReduceSum(qv * qv, sh);
    float sk = blockReduceSum(kv * kv, sh);

    float g = ghead[i];
    size_t o = (size_t)bid * HD + i;
    float qn = qv * rsqrtf(sq * (1.0f / HD) + EPSV) * g * ATT_SCALE;
    float kn = kv * rsqrtf(sk * (1.0f / HD) + EPSV) * g;
    d_qn[o] = __float2half(qn);
    d_kn[o] = __float2half(kn);
}

__global__ void vtrans_kernel(const float* __restrict__ bkv) {
    __shared__ float tile[32][33];
    int bh = blockIdx.z;
    int b = bh >> 4, h = bh & 15;
    int t0 = blockIdx.x * 32, i0 = blockIdx.y * 32;
    for (int j = threadIdx.y; j < 32; j += 8)
        tile[j][threadIdx.x] =
            d_qkvlin[(size_t)(b * TT + t0 + j) * NQKV + 2 * DD + h * HD + i0 + threadIdx.x];
    __syncthreads();
    for (int j = threadIdx.y; j < 32; j += 8) {
        float v = tile[threadIdx.x][j] + bkv[DD + h * HD + i0 + j];
        size_t o = ((size_t)bh * HD + i0 + j) * TT + t0 + threadIdx.x;
        d_vt[o] = __float2half(v);
    }
}

// ---------------- launch ----------------
template<typename T> static T* symaddr(const void* sym) {
    void* p = nullptr;
    cudaGetSymbolAddress(&p, sym);
    return (T*)p;
}

extern "C" void kernel_launch(void* const* d_in, const int* in_sizes, int n_in,
                              void* d_out, int out_size) {
    const float* x   = (const float*)d_in[0];
    const float* gq  = (const float*)d_in[1];
    const float* Wq  = (const float*)d_in[2];
    const float* bq  = (const float*)d_in[3];
    const float* gkv = (const float*)d_in[4];
    const float* Wkv = (const float*)d_in[5];
    const float* bkv = (const float*)d_in[6];
    const float* gh  = (const float*)d_in[7];
    const float* Wo  = (const float*)d_in[8];
    const float* bo  = (const float*)d_in[9];
    float* out = (float*)d_out;

    hf* xn   = symaddr<hf>(d_xn);
    hf* wc_h = symaddr<hf>(d_wc_h);  hf* wc_l = symaddr<hf>(d_wc_l);
    hf* wo_h = symaddr<hf>(d_wo_h);  hf* wo_l = symaddr<hf>(d_wo_l);
    float* qkvlin = symaddr<float>(d_qkvlin);
    hf* wvt  = symaddr<hf>(d_wvt);

    cudaFuncSetAttribute(mma_gemm<false>, cudaFuncAttributeMaxDynamicSharedMemorySize, G_SMEM);
    cudaFuncSetAttribute(mma_gemm<true>,  cudaFuncAttributeMaxDynamicSharedMemorySize, G_SMEM);
    cudaFuncSetAttribute(flash_kernel,    cudaFuncAttributeMaxDynamicSharedMemorySize, SMEM_FLASH);

    // 1-2. weight transpose+split with gain fold
    wtransg_kernel<<<dim3(DD / 32, DD / 32), dim3(32, 8)>>>(Wq, gq, wc_h, wc_l, DD, 0);
    wtransg_kernel<<<dim3(2 * DD / 32, DD / 32), dim3(32, 8)>>>(Wkv, gkv, wc_h, wc_l, 2 * DD, DD);

    // 3. RMSNorm -> fp16 activation (hi only)
    rmsnorm_kernel<<<ROWS, 256>>>(x);

    // 4. fused QKV projection: [4096,2048] x [6144,2048]^T  (ncu capture target)
    mma_gemm<false><<<dim3(NQKV / 128, ROWS / 64), 128, G_SMEM>>>(
        xn, wc_h, wc_l, nullptr, qkvlin, DD, NQKV, 1.0f);

    // 5-6. per-head RMSNorm (+bias) and v transpose (+bias), all hi-only
    head_rms_kernel<<<BB * HH * TT, HD>>>(gh, bq, bkv);
    vtrans_kernel<<<dim3(TT / 32, HD / 32, BB * HH), dim3(32, 8)>>>(bkv);

    // 7. fused flash attention (all-fp16) -> d_wvt
    flash_kernel<<<dim3(TT / 128, BB * HH), 256, SMEM_FLASH>>>();

    // 8. O weight transpose
    wtransg_kernel<<<dim3(DD / 32, DD / 32), dim3(32, 8)>>>(Wo, nullptr, wo_h, wo_l, DD, 0);

    // 9. out = wvt @ Wo^T + bo
    mma_gemm<true><<<dim3(DD / 128, ROWS / 64), 128, G_SMEM>>>(
        wvt, wo_h, wo_l, bo, out, DD, DD, 1.0f);
}

// round 17
// speedup vs baseline: 2.3484x; 1.4380x over previous
#include <cuda_runtime.h>
#include <cuda_fp16.h>
#include <cstdint>
#include <math.h>

#define BB 2
#define TT 2048
#define DD 2048
#define HH 16
#define HD 128
#define ROWS (BB*TT)              // 4096
#define NQKV (3*DD)               // 6144
#define EPSV 1.1920929e-07f
#define ATT_SCALE 0.088388347648318447f   // 1/sqrt(128)

typedef __half hf;

// ---------------- scratch (device globals) ----------------
__device__ __align__(256) hf d_xn  [ROWS*DD];                            // rms(x)
__device__ __align__(256) hf d_wc  [NQKV*DD];                            // [6144,K] gains folded
__device__ __align__(256) hf d_wo  [DD*DD];                              // [N,K]
__device__ __align__(256) float d_qkvlin[ROWS*NQKV];                     // [4096,6144]
__device__ __align__(256) hf d_qn  [BB*HH*TT*HD];                        // [B,H,T,d]
__device__ __align__(256) hf d_kn  [BB*HH*TT*HD];                        // [B,H,T,d]
__device__ __align__(256) hf d_vt  [BB*HH*HD*TT];                        // [B,H,d,T]
__device__ __align__(256) hf d_wvt [ROWS*DD];                            // [B*T, D]

// ---------------- helpers ----------------
__device__ __forceinline__ uint32_t pack_h2(hf a, hf b) {
    __half2 t = __halves2half2(a, b);
    return *(uint32_t*)&t;
}

__device__ __forceinline__ float blockReduceSum(float v, float* sh) {
    __syncthreads();
    int lane = threadIdx.x & 31, w = threadIdx.x >> 5;
    #pragma unroll
    for (int o = 16; o > 0; o >>= 1) v += __shfl_down_sync(0xffffffffu, v, o);
    if (lane == 0) sh[w] = v;
    __syncthreads();
    int nw = blockDim.x >> 5;
    v = (threadIdx.x < nw) ? sh[threadIdx.x] : 0.0f;
    if (w == 0) {
        #pragma unroll
        for (int o = 16; o > 0; o >>= 1) v += __shfl_down_sync(0xffffffffu, v, o);
        if (lane == 0) sh[0] = v;
    }
    __syncthreads();
    return sh[0];
}

__device__ __forceinline__ uint32_t smem_u32(const void* p) {
    return (uint32_t)__cvta_generic_to_shared(p);
}

__device__ __forceinline__ void ldsm4(uint32_t addr, uint32_t* r) {
    asm volatile("ldmatrix.sync.aligned.m8n8.x4.shared.b16 {%0,%1,%2,%3}, [%4];"
                 : "=r"(r[0]), "=r"(r[1]), "=r"(r[2]), "=r"(r[3]) : "r"(addr));
}

__device__ __forceinline__ void mma16816(float* c, const uint32_t* a, const uint32_t* b) {
    asm volatile("mma.sync.aligned.m16n8k16.row.col.f32.f16.f16.f32 "
                 "{%0,%1,%2,%3}, {%4,%5,%6,%7}, {%8,%9}, {%0,%1,%2,%3};"
                 : "+f"(c[0]), "+f"(c[1]), "+f"(c[2]), "+f"(c[3])
                 : "r"(a[0]), "r"(a[1]), "r"(a[2]), "r"(a[3]), "r"(b[0]), "r"(b[1]));
}

__device__ __forceinline__ void cpasync16(uint32_t dst, const void* src) {
    asm volatile("cp.async.cg.shared.global [%0], [%1], 16;" :: "r"(dst), "l"(src));
}
__device__ __forceinline__ void cpcommit() {
    asm volatile("cp.async.commit_group;" ::: "memory");
}
template<int N> __device__ __forceinline__ void cpwait() {
    asm volatile("cp.async.wait_group %0;" :: "n"(N) : "memory");
}

// ---------------- fp16 GEMM: 64x128 block, 128 threads (2x2 warps) ----------------
// C[M,N] = alpha*(A @ Bt^T)(+bias). A:[M,K] fp16; Bt:[N,K] fp16. 1 MMA per k16.
// Per stage: A 8KB | B 16KB = 24KB. 2 stages = 48KB.
#define G_STAGE 24576
#define G_SMEM  (2*G_STAGE)
#define OFF_B   8192

template<bool HAS_BIAS>
__global__ __launch_bounds__(128, 2)
void mma_gemm(const hf* __restrict__ A, const hf* __restrict__ B,
              const float* __restrict__ bias, float* __restrict__ C,
              int K, int ldc, float alpha) {
    extern __shared__ char smem[];
    const uint32_t sb = smem_u32(smem);
    const int tid = threadIdx.x, lane = tid & 31, w = tid >> 5;
    const int wm = w >> 1, wn = w & 1;          // warp grid 2(M) x 2(N)
    const int bm = blockIdx.y * 64, bn = blockIdx.x * 128;

    const hf* aSrc = A + (size_t)bm * K;
    const hf* bSrc = B + (size_t)bn * K;

    float acc[2][8][4];
    #pragma unroll
    for (int t = 0; t < 2; t++)
        #pragma unroll
        for (int n = 0; n < 8; n++)
            #pragma unroll
            for (int r = 0; r < 4; r++) acc[t][n][r] = 0.0f;

    const int NC = K >> 6;

    auto issue_load = [&](int stage, int kc) {
        const uint32_t base = sb + stage * G_STAGE;
        const int k0 = kc << 6;
        {                                        // A: 64 rows x 8 cols of 16B
            const hf* sp = aSrc + k0;
            #pragma unroll
            for (int j = 0; j < 4; j++) {
                int f = tid + j * 128;
                int r = f >> 3, c = f & 7;
                cpasync16(base + (uint32_t)(r * 128 + ((c ^ (r & 7)) << 4)),
                          sp + (size_t)r * K + c * 8);
            }
        }
        {                                        // B: 128 rows x 8 cols of 16B
            const hf* sp = bSrc + k0;
            const uint32_t tb = base + OFF_B;
            #pragma unroll
            for (int j = 0; j < 8; j++) {
                int f = tid + j * 128;
                int r = f >> 3, c = f & 7;
                cpasync16(tb + (uint32_t)(r * 128 + ((c ^ (r & 7)) << 4)),
                          sp + (size_t)r * K + c * 8);
            }
        }
        cpcommit();
    };

    issue_load(0, 0);
    for (int kc = 0; kc < NC; kc++) {
        const int cur = kc & 1;
        if (kc + 1 < NC) { issue_load(cur ^ 1, kc + 1); cpwait<1>(); }
        else             { cpwait<0>(); }
        __syncthreads();

        const uint32_t baseA = sb + cur * G_STAGE;
        const uint32_t baseB = baseA + OFF_B;
        #pragma unroll
        for (int s = 0; s < 4; s++) {
            uint32_t aH[2][4], bH[8][2];
            #pragma unroll
            for (int t = 0; t < 2; t++) {
                int m = wm * 32 + t * 16 + (lane & 15);
                uint32_t off = (uint32_t)(m * 128 + (((s * 2 + (lane >> 4)) ^ (m & 7)) << 4));
                ldsm4(baseA + off, aH[t]);
            }
            #pragma unroll
            for (int u = 0; u < 4; u++) {
                int n = wn * 64 + u * 16 + (lane & 15);
                uint32_t off = (uint32_t)(n * 128 + (((s * 2 + (lane >> 4)) ^ (n & 7)) << 4));
                uint32_t r4[4];
                ldsm4(baseB + off, r4);
                bH[2*u][0] = r4[0]; bH[2*u+1][0] = r4[1];
                bH[2*u][1] = r4[2]; bH[2*u+1][1] = r4[3];
            }
            #pragma unroll
            for (int t = 0; t < 2; t++)
                #pragma unroll
                for (int n = 0; n < 8; n++)
                    mma16816(acc[t][n], aH[t], bH[n]);
        }
        __syncthreads();
    }

    #pragma unroll
    for (int t = 0; t < 2; t++) {
        #pragma unroll
        for (int n = 0; n < 8; n++) {
            int m0 = bm + wm * 32 + t * 16 + (lane >> 2);
            int n0 = bn + wn * 64 + n * 8 + 2 * (lane & 3);
            float bx = 0.0f, by = 0.0f;
            if (HAS_BIAS) { bx = bias[n0]; by = bias[n0 + 1]; }
            float2 v0 = { acc[t][n][0] * alpha + bx, acc[t][n][1] * alpha + by };
            float2 v1 = { acc[t][n][2] * alpha + bx, acc[t][n][3] * alpha + by };
            *(float2*)(C + (size_t)m0 * ldc + n0) = v0;
            *(float2*)(C + (size_t)(m0 + 8) * ldc + n0) = v1;
        }
    }
}

// ---------------- fused flash attention (all fp16, unchanged from round 15) ----------
#define FSEG 32768
#define SMEM_FLASH (3*FSEG)                 // Kh | Vh | Qh

__device__ __forceinline__ uint32_t swz(int r, int c) {
    return (uint32_t)(r * 256 + (((c & 8) | ((c ^ r) & 7)) << 4));
}

__global__ __launch_bounds__(256, 1)
void flash_kernel() {
    extern __shared__ char smem[];
    const uint32_t sb = smem_u32(smem);
    const uint32_t sKh = sb, sVh = sb + FSEG, sQh = sb + 2*FSEG;

    const int tid = threadIdx.x, lane = tid & 31, w = tid >> 5;
    const int bh = blockIdx.y;
    const int q0 = blockIdx.x * 128;

    const hf* qh = d_qn + (size_t)bh * TT * HD + (size_t)q0 * HD;
    const hf* kh = d_kn + (size_t)bh * TT * HD;
    const hf* vh = d_vt + (size_t)bh * HD * TT;

    auto loadT = [&](uint32_t dstb, const hf* src, int rowStride) {
        #pragma unroll
        for (int j = 0; j < 8; j++) {
            int f = tid + j * 256;
            int r = f >> 4, c = f & 15;
            cpasync16(dstb + swz(r, c), src + (size_t)r * rowStride + c * 8);
        }
    };

    loadT(sQh, qh, HD);
    loadT(sKh, kh, HD);
    loadT(sVh, vh, TT);
    cpcommit();
    cpwait<0>();
    __syncthreads();

    float o[16][4];
    #pragma unroll
    for (int f = 0; f < 16; f++)
        #pragma unroll
        for (int j = 0; j < 4; j++) o[f][j] = 0.0f;
    float mrow[2] = {-INFINITY, -INFINITY};
    float lrow[2] = {0.0f, 0.0f};

    const int NT = TT / 128;
    for (int i = 0; i < NT; i++) {
        float sacc[16][4];
        #pragma unroll
        for (int f = 0; f < 16; f++)
            #pragma unroll
            for (int j = 0; j < 4; j++) sacc[f][j] = 0.0f;

        #pragma unroll
        for (int s = 0; s < 8; s++) {
            const int mR = (w << 4) + (lane & 15);
            const int cc = 2 * s + (lane >> 4);
            uint32_t aH[4];
            ldsm4(sQh + swz(mR, cc), aH);
            #pragma unroll
            for (int u = 0; u < 8; u++) {
                const int n = u * 16 + (lane & 15);
                uint32_t r4h[4];
                ldsm4(sKh + swz(n, cc), r4h);
                uint32_t b0h[2] = {r4h[0], r4h[2]}, b1h[2] = {r4h[1], r4h[3]};
                mma16816(sacc[2*u],   aH, b0h);
                mma16816(sacc[2*u+1], aH, b1h);
            }
        }
        __syncthreads();
        if (i + 1 < NT) { loadT(sKh, kh + (size_t)(i+1)*128*HD, HD); cpcommit(); }

        float mnew[2] = {mrow[0], mrow[1]};
        #pragma unroll
        for (int f = 0; f < 16; f++) {
            mnew[0] = fmaxf(mnew[0], fmaxf(sacc[f][0], sacc[f][1]));
            mnew[1] = fmaxf(mnew[1], fmaxf(sacc[f][2], sacc[f][3]));
        }
        #pragma unroll
        for (int rr = 0; rr < 2; rr++) {
            mnew[rr] = fmaxf(mnew[rr], __shfl_xor_sync(0xffffffffu, mnew[rr], 1));
            mnew[rr] = fmaxf(mnew[rr], __shfl_xor_sync(0xffffffffu, mnew[rr], 2));
        }
        float resc[2] = { __expf(mrow[0] - mnew[0]), __expf(mrow[1] - mnew[1]) };
        mrow[0] = mnew[0]; mrow[1] = mnew[1];
        float psum[2] = {0.0f, 0.0f};
        #pragma unroll
        for (int f = 0; f < 16; f++) {
            sacc[f][0] = __expf(sacc[f][0] - mrow[0]);
            sacc[f][1] = __expf(sacc[f][1] - mrow[0]);
            sacc[f][2] = __expf(sacc[f][2] - mrow[1]);
            sacc[f][3] = __expf(sacc[f][3] - mrow[1]);
            psum[0] += sacc[f][0] + sacc[f][1];
            psum[1] += sacc[f][2] + sacc[f][3];
        }
        #pragma unroll
        for (int rr = 0; rr < 2; rr++) {
            psum[rr] += __shfl_xor_sync(0xffffffffu, psum[rr], 1);
            psum[rr] += __shfl_xor_sync(0xffffffffu, psum[rr], 2);
        }
        lrow[0] = lrow[0] * resc[0] + psum[0];
        lrow[1] = lrow[1] * resc[1] + psum[1];
        #pragma unroll
        for (int f = 0; f < 16; f++) {
            o[f][0] *= resc[0]; o[f][1] *= resc[0];
            o[f][2] *= resc[1]; o[f][3] *= resc[1];
        }

        if (i > 0) {
            if (i + 1 < NT) cpwait<1>(); else cpwait<0>();
            __syncthreads();
        }

        #pragma unroll
        for (int s = 0; s < 8; s++) {
            const int f0 = 2 * s, f1 = 2 * s + 1;
            uint32_t aPh[4];
            aPh[0] = pack_h2(__float2half(sacc[f0][0]), __float2half(sacc[f0][1]));
            aPh[1] = pack_h2(__float2half(sacc[f0][2]), __float2half(sacc[f0][3]));
            aPh[2] = pack_h2(__float2half(sacc[f1][0]), __float2half(sacc[f1][1]));
            aPh[3] = pack_h2(__float2half(sacc[f1][2]), __float2half(sacc[f1][3]));
            const int cc = 2 * s + (lane >> 4);
            #pragma unroll
            for (int u = 0; u < 8; u++) {
                const int n = u * 16 + (lane & 15);
                uint32_t r4h[4];
                ldsm4(sVh + swz(n, cc), r4h);
                uint32_t b0h[2] = {r4h[0], r4h[2]}, b1h[2] = {r4h[1], r4h[3]};
                mma16816(o[2*u],   aPh, b0h);
                mma16816(o[2*u+1], aPh, b1h);
            }
        }
        __syncthreads();
        if (i + 1 < NT) {
            loadT(sVh, vh + (size_t)(i+1)*128, TT);
            cpcommit();
            cpwait<1>();
            __syncthreads();
        }
    }

    const int b = bh >> 4, h = bh & 15;
    const float inv0 = 1.0f / lrow[0], inv1 = 1.0f / lrow[1];
    const int r0 = (w << 4) + (lane >> 2);
    const size_t bt0 = (size_t)(b * TT + q0 + r0) * DD;
    const size_t bt1 = (size_t)(b * TT + q0 + r0 + 8) * DD;
    const int colb = h * HD + 2 * (lane & 3);
    #pragma unroll
    for (int f = 0; f < 16; f++) {
        const int col = colb + f * 8;
        *(uint32_t*)(d_wvt + bt0 + col) =
            pack_h2(__float2half(o[f][0] * inv0), __float2half(o[f][1] * inv0));
        *(uint32_t*)(d_wvt + bt1 + col) =
            pack_h2(__float2half(o[f][2] * inv1), __float2half(o[f][3] * inv1));
    }
}

// ---------------- elementwise producers ----------------
__global__ void rmsnorm_kernel(const float* __restrict__ x) {
    int row = blockIdx.x;
    const float* xr = x + (size_t)row * DD;
    float s = 0.0f;
    for (int c = threadIdx.x; c < DD; c += blockDim.x) { float v = xr[c]; s += v * v; }
    __shared__ float sh[32];
    s = blockReduceSum(s, sh);
    float inv = rsqrtf(s * (1.0f / DD) + EPSV);
    for (int c = threadIdx.x; c < DD; c += blockDim.x) {
        d_xn[(size_t)row * DD + c] = __float2half(xr[c] * inv);
    }
}

// W[K,Nd] fp32 -> dest[(rowOff+n), k] fp16 with optional per-k gain fold
__global__ void wtransg_kernel(const float* __restrict__ W, const float* __restrict__ g,
                               hf* __restrict__ T, int Nd, int rowOff) {
    __shared__ float tile[32][33];
    int k0 = blockIdx.y * 32, n0 = blockIdx.x * 32;
    for (int j = threadIdx.y; j < 32; j += 8)
        tile[j][threadIdx.x] = W[(size_t)(k0 + j) * Nd + n0 + threadIdx.x];
    __syncthreads();
    float gv = g ? g[k0 + threadIdx.x] : 1.0f;
    for (int j = threadIdx.y; j < 32; j += 8) {
        float v = tile[threadIdx.x][j] * gv;
        T[(size_t)(rowOff + n0 + j) * DD + k0 + threadIdx.x] = __float2half(v);
    }
}

__global__ void head_rms_kernel(const float* __restrict__ ghead,
                                const float* __restrict__ bq,
                                const float* __restrict__ bkv) {
    int bid = blockIdx.x;
    int t = bid & (TT - 1);
    int bh = bid / TT;
    int h = bh & (HH - 1);
    int b = bh / HH;
    int bt = b * TT + t;
    int i = threadIdx.x;
    int col = h * HD + i;

    float qv = d_qkvlin[(size_t)bt * NQKV + col] + bq[col];
    float kv = d_qkvlin[(size_t)bt * NQKV + DD + col] + bkv[col];

    __shared__ float sh[32];
    float sq = blockReduceSum(qv * qv, sh);
    float sk = blockReduceSum(kv * kv, sh);

    float g = ghead[i];
    size_t o = (size_t)bid * HD + i;
    float qn = qv * rsqrtf(sq * (1.0f / HD) + EPSV) * g * ATT_SCALE;
    float kn = kv * rsqrtf(sk * (1.0f / HD) + EPSV) * g;
    d_qn[o] = __float2half(qn);
    d_kn[o] = __float2half(kn);
}

__global__ void vtrans_kernel(const float* __restrict__ bkv) {
    __shared__ float tile[32][33];
    int bh = blockIdx.z;
    int b = bh >> 4, h = bh & 15;
    int t0 = blockIdx.x * 32, i0 = blockIdx.y * 32;
    for (int j = threadIdx.y; j < 32; j += 8)
        tile[j][threadIdx.x] =
            d_qkvlin[(size_t)(b * TT + t0 + j) * NQKV + 2 * DD + h * HD + i0 + threadIdx.x];
    __syncthreads();
    for (int j = threadIdx.y; j < 32; j += 8) {
        float v = tile[threadIdx.x][j] + bkv[DD + h * HD + i0 + j];
        size_t o = ((size_t)bh * HD + i0 + j) * TT + t0 + threadIdx.x;
        d_vt[o] = __float2half(v);
    }
}

// ---------------- launch ----------------
template<typename T> static T* symaddr(const void* sym) {
    void* p = nullptr;
    cudaGetSymbolAddress(&p, sym);
    return (T*)p;
}

extern "C" void kernel_launch(void* const* d_in, const int* in_sizes, int n_in,
                              void* d_out, int out_size) {
    const float* x   = (const float*)d_in[0];
    const float* gq  = (const float*)d_in[1];
    const float* Wq  = (const float*)d_in[2];
    const float* bq  = (const float*)d_in[3];
    const float* gkv = (const float*)d_in[4];
    const float* Wkv = (const float*)d_in[5];
    const float* bkv = (const float*)d_in[6];
    const float* gh  = (const float*)d_in[7];
    const float* Wo  = (const float*)d_in[8];
    const float* bo  = (const float*)d_in[9];
    float* out = (float*)d_out;

    hf* xn  = symaddr<hf>(d_xn);
    hf* wc  = symaddr<hf>(d_wc);
    hf* wo  = symaddr<hf>(d_wo);
    float* qkvlin = symaddr<float>(d_qkvlin);
    hf* wvt = symaddr<hf>(d_wvt);

    cudaFuncSetAttribute(mma_gemm<false>, cudaFuncAttributeMaxDynamicSharedMemorySize, G_SMEM);
    cudaFuncSetAttribute(mma_gemm<true>,  cudaFuncAttributeMaxDynamicSharedMemorySize, G_SMEM);
    cudaFuncSetAttribute(flash_kernel,    cudaFuncAttributeMaxDynamicSharedMemorySize, SMEM_FLASH);

    // 1-2. weight transpose with gain fold (fp16)
    wtransg_kernel<<<dim3(DD / 32, DD / 32), dim3(32, 8)>>>(Wq, gq, wc, DD, 0);
    wtransg_kernel<<<dim3(2 * DD / 32, DD / 32), dim3(32, 8)>>>(Wkv, gkv, wc, 2 * DD, DD);

    // 3. RMSNorm -> fp16 activation
    rmsnorm_kernel<<<ROWS, 256>>>(x);

    // 4. fused QKV projection: [4096,2048] x [6144,2048]^T  (ncu capture target)
    mma_gemm<false><<<dim3(NQKV / 128, ROWS / 64), 128, G_SMEM>>>(
        xn, wc, nullptr, qkvlin, DD, NQKV, 1.0f);

    // 5-6. per-head RMSNorm (+bias) and v transpose (+bias)
    head_rms_kernel<<<BB * HH * TT, HD>>>(gh, bq, bkv);
    vtrans_kernel<<<dim3(TT / 32, HD / 32, BB * HH), dim3(32, 8)>>>(bkv);

    // 7. fused flash attention (all-fp16) -> d_wvt
    flash_kernel<<<dim3(TT / 128, BB * HH), 256, SMEM_FLASH>>>();

    // 8. O weight transpose
    wtransg_kernel<<<dim3(DD / 32, DD / 32), dim3(32, 8)>>>(Wo, nullptr, wo, DD, 0);

    // 9. out = wvt @ Wo^T + bo
    mma_gemm<true><<<dim3(DD / 128, ROWS / 64), 128, G_SMEM>>>(
        wvt, wo, bo, out, DD, DD, 1.0f);
}